// round 8
// baseline (speedup 1.0000x reference)
#include <cuda_runtime.h>
#include <cstdint>
#include <math.h>

#define BETA   5.5f
#define NC     1000
#define NM     50
#define NR     51        // rows incl. vanilla
#define ND     1024
#define ND4    256
#define QB     125
#define QROWS  8
#define NW     8         // warps per CTA

__device__ __align__(16) float g_qn[ND];
__device__ float g_logits[NC];
__device__ float g_qpart[QB * ND];
__device__ unsigned int g_ctr_q = 0;
__device__ unsigned int g_ctr_m = 0;

__device__ __forceinline__ float dot4(const float4 a, const float4 b)
{
    return a.x * b.x + a.y * b.y + a.z * b.z + a.w * b.w;
}

// ---------------------------------------------------------------------------
// Kernel 1: qn = l2norm(img + mean(global_bias,0)). grid=125 x 1024, ticketed.
// ---------------------------------------------------------------------------
__global__ void qn_kernel(const float* __restrict__ gb,
                          const float* __restrict__ img)
{
    const int d = threadIdx.x;
    const int b = blockIdx.x;
    const float* base = gb + (size_t)b * QROWS * ND + d;
    float s = 0.0f;
    #pragma unroll
    for (int r = 0; r < QROWS; ++r) s += base[r * ND];
    g_qpart[b * ND + d] = s;

    __shared__ unsigned int ticket;
    __threadfence();
    __syncthreads();
    if (d == 0) ticket = atomicAdd(&g_ctr_q, 1u);
    __syncthreads();
    if (ticket != QB - 1) return;

    float tsum = 0.0f;
    #pragma unroll 5
    for (int bb = 0; bb < QB; ++bb) tsum += g_qpart[bb * ND + d];
    const float q = img[d] + tsum * (1.0f / (float)NC);

    __shared__ float red[32];
    float v = q * q;
    #pragma unroll
    for (int o = 16; o; o >>= 1) v += __shfl_xor_sync(0xffffffffu, v, o);
    const int w = d >> 5, lane = d & 31;
    if (lane == 0) red[w] = v;
    __syncthreads();
    float tot = 0.0f;
    #pragma unroll
    for (int i = 0; i < 32; ++i) tot += red[i];

    g_qn[d] = q * rsqrtf(tot);
    if (d == 0) g_ctr_q = 0;
}

// ---------------------------------------------------------------------------
// Kernel 2: per-class attention. grid=1000, block=256 (8 warps), 2 CTA/SM.
// Warp wi handles rows m = wi, wi+8, ... (row 50 = vanilla).
// Single row buffer (latency hidden by 16 warps/SM), no mainloop barriers.
// Last CTA runs the softmax.
// ---------------------------------------------------------------------------
__global__ void __launch_bounds__(256, 2)
dualmem_main_kernel(const float* __restrict__ mem,
                    const float* __restrict__ van,
                    const float* __restrict__ gbk,
                    const float* __restrict__ gbv,
                    const float* __restrict__ ffn,
                    const float* __restrict__ img,
                    const float* __restrict__ scale,
                    float* __restrict__ out)
{
    __shared__ float4 qn_s[ND4];
    __shared__ float4 bk_s[ND4];
    __shared__ float4 bv_s[ND4];
    __shared__ float4 accs[NW][ND4];      // 32 KB combine scratch
    __shared__ float  sw_s[NW];
    __shared__ float4 redc[NW];
    __shared__ float  red1[NW];
    __shared__ float2 red2[NW];
    __shared__ float  redm[NW], reds[NW];
    __shared__ unsigned int ticket;

    const int c    = blockIdx.x;
    const int t    = threadIdx.x;       // 0..255
    const int wi   = t >> 5;            // 0..7
    const int lane = t & 31;

    const float4* qn4  = (const float4*)g_qn;
    const float4* gbk4 = (const float4*)(gbk + (size_t)c * ND);
    const float4* gbv4 = (const float4*)(gbv + (size_t)c * ND);
    const float4* mem4 = (const float4*)(mem + (size_t)c * NM * ND);
    const float4* van4 = (const float4*)(van + (size_t)c * ND);

    // stage qn/bk/bv (one float4 per thread) + per-class constants
    {
        const float4 q = qn4[t];
        const float4 k = gbk4[t];
        const float4 v = gbv4[t];
        qn_s[t] = q; bk_s[t] = k; bv_s[t] = v;
        float pqk = dot4(q, k);
        float pkk = dot4(k, k);
        float pvv = dot4(v, v);
        #pragma unroll
        for (int o = 16; o; o >>= 1) {
            pqk += __shfl_xor_sync(0xffffffffu, pqk, o);
            pkk += __shfl_xor_sync(0xffffffffu, pkk, o);
            pvv += __shfl_xor_sync(0xffffffffu, pvv, o);
        }
        if (lane == 0) redc[wi] = make_float4(pqk, pkk, pvv, 0.0f);
    }
    __syncthreads();
    float qk_c = 0.0f, kk_c = 0.0f, vv_c = 0.0f;
    #pragma unroll
    for (int i = 0; i < NW; ++i) {
        qk_c += redc[i].x; kk_c += redc[i].y; vv_c += redc[i].z;
    }

    // --- mainloop: single row buffer, stride NW, no block barriers ---
    float4 acc[8];
    #pragma unroll
    for (int j = 0; j < 8; ++j) acc[j] = make_float4(0.f, 0.f, 0.f, 0.f);
    float sw = 0.0f;

    for (int m = wi; m < NR; m += NW) {
        const float4* r = (m < NM) ? (mem4 + (size_t)m * ND4) : van4;
        float4 x[8];
        #pragma unroll
        for (int j = 0; j < 8; ++j) x[j] = r[j * 32 + lane];

        float xx = 0.f, qx = 0.f, xk = 0.f, xv = 0.f;
        #pragma unroll
        for (int j = 0; j < 8; ++j) {
            const int idx = j * 32 + lane;
            const float4 q = qn_s[idx];
            const float4 k = bk_s[idx];
            const float4 v = bv_s[idx];
            xx += dot4(x[j], x[j]);
            qx += dot4(q, x[j]);
            xk += dot4(k, x[j]);
            xv += dot4(v, x[j]);
        }
        #pragma unroll
        for (int o = 16; o; o >>= 1) {
            xx += __shfl_xor_sync(0xffffffffu, xx, o);
            qx += __shfl_xor_sync(0xffffffffu, qx, o);
            xk += __shfl_xor_sync(0xffffffffu, xk, o);
            xv += __shfl_xor_sync(0xffffffffu, xv, o);
        }

        float w = 0.0f;
        if (xx != 0.0f) {                  // all-zero row <=> |x|^2 == 0
            const float dq = qx + qk_c;
            const float k2 = xx + 2.0f * xk + kk_c;
            const float v2 = xx + 2.0f * xv + vv_c;
            w = __expf(-BETA * (1.0f - dq * rsqrtf(k2))) * rsqrtf(v2);
        }
        sw += w;
        #pragma unroll
        for (int j = 0; j < 8; ++j) {
            acc[j].x += w * x[j].x;
            acc[j].y += w * x[j].y;
            acc[j].z += w * x[j].z;
            acc[j].w += w * x[j].w;
        }
    }

    // --- combine warps: acc_total = sum_w acc + sw_total * bv ---
    #pragma unroll
    for (int j = 0; j < 8; ++j) accs[wi][j * 32 + lane] = acc[j];
    if (lane == 0) sw_s[wi] = sw;
    __syncthreads();

    float swt = 0.0f;
    #pragma unroll
    for (int i = 0; i < NW; ++i) swt += sw_s[i];

    float4 s = accs[0][t];
    #pragma unroll
    for (int w = 1; w < NW; ++w) {
        const float4 p = accs[w][t];
        s.x += p.x; s.y += p.y; s.z += p.z; s.w += p.w;
    }
    const float4 b0 = bv_s[t];
    s.x += swt * b0.x; s.y += swt * b0.y; s.z += swt * b0.z; s.w += swt * b0.w;

    // l2norm(acc)
    float n1 = dot4(s, s);
    #pragma unroll
    for (int o = 16; o; o >>= 1) n1 += __shfl_xor_sync(0xffffffffu, n1, o);
    if (lane == 0) red1[wi] = n1;
    __syncthreads();
    float n1t = 0.0f;
    #pragma unroll
    for (int i = 0; i < NW; ++i) n1t += red1[i];
    const float rin1 = rsqrtf(n1t);

    // + ffn, l2norm, dot img
    const float4 f0 = ((const float4*)(ffn + (size_t)c * ND))[t];
    const float4 i0 = ((const float4*)img)[t];
    const float4 af = make_float4(s.x * rin1 + f0.x, s.y * rin1 + f0.y,
                                  s.z * rin1 + f0.z, s.w * rin1 + f0.w);

    float n2 = dot4(af, af);
    float dp = dot4(af, i0);
    #pragma unroll
    for (int o = 16; o; o >>= 1) {
        n2 += __shfl_xor_sync(0xffffffffu, n2, o);
        dp += __shfl_xor_sync(0xffffffffu, dp, o);
    }
    if (lane == 0) red2[wi] = make_float2(n2, dp);
    __syncthreads();

    if (t == 0) {
        float n2t = 0.0f, dpt = 0.0f;
        #pragma unroll
        for (int i = 0; i < NW; ++i) { n2t += red2[i].x; dpt += red2[i].y; }
        g_logits[c] = expf(scale[0]) * dpt * rsqrtf(n2t);
    }

    // --- last CTA: softmax over g_logits ---
    __threadfence();
    __syncthreads();
    if (t == 0) ticket = atomicAdd(&g_ctr_m, 1u);
    __syncthreads();
    if (ticket != NC - 1) return;

    float x[4];
    #pragma unroll
    for (int k = 0; k < 4; ++k) {
        const int i = t + k * 256;
        x[k] = (i < NC) ? g_logits[i] : -INFINITY;
    }
    float mx = fmaxf(fmaxf(x[0], x[1]), fmaxf(x[2], x[3]));
    #pragma unroll
    for (int o = 16; o; o >>= 1) mx = fmaxf(mx, __shfl_xor_sync(0xffffffffu, mx, o));
    if (lane == 0) redm[wi] = mx;
    __syncthreads();
    mx = redm[0];
    #pragma unroll
    for (int i = 1; i < NW; ++i) mx = fmaxf(mx, redm[i]);

    float e[4];
    float es = 0.0f;
    #pragma unroll
    for (int k = 0; k < 4; ++k) {
        const int i = t + k * 256;
        e[k] = (i < NC) ? expf(x[k] - mx) : 0.0f;
        es += e[k];
    }
    #pragma unroll
    for (int o = 16; o; o >>= 1) es += __shfl_xor_sync(0xffffffffu, es, o);
    if (lane == 0) reds[wi] = es;
    __syncthreads();
    float stot = 0.0f;
    #pragma unroll
    for (int i = 0; i < NW; ++i) stot += reds[i];
    const float rst = 1.0f / stot;

    #pragma unroll
    for (int k = 0; k < 4; ++k) {
        const int i = t + k * 256;
        if (i < NC) out[i] = e[k] * rst;
    }
    if (t == 0) g_ctr_m = 0;
}

// ---------------------------------------------------------------------------
extern "C" void kernel_launch(void* const* d_in, const int* in_sizes, int n_in,
                              void* d_out, int out_size)
{
    const float* img   = (const float*)d_in[0];
    const float* mem   = (const float*)d_in[1];
    const float* van   = (const float*)d_in[2];
    const float* gb    = (const float*)d_in[3];
    const float* gbk   = (const float*)d_in[4];
    const float* gbv   = (const float*)d_in[5];
    const float* ffn   = (const float*)d_in[6];
    const float* scale = (const float*)d_in[7];

    qn_kernel<<<QB, 1024>>>(gb, img);
    dualmem_main_kernel<<<NC, 256>>>(mem, van, gbk, gbv, ffn, img, scale,
                                     (float*)d_out);
}